// round 8
// baseline (speedup 1.0000x reference)
#include <cuda_runtime.h>
#include <cuda_fp16.h>
#include <stdint.h>

// ---------------------------------------------------------------------------
// LightGCN: N=100000, D=64, E=1000000, 3 layers.
// out[0:ND] = E0 ; out[ND:2ND] = (E0 + x1 + x2 + x3)/4
//
// y = dinv (.) x stored fp16. Propagate: WARP PER NODE; 32 source indices are
// staged per chunk with ONE coalesced load, broadcast via shfl, so all gathers
// in a chunk are independent (MLP = 4-bank unroll, no dependent-load chain).
// Lane owns one half2 (features 2*lane, 2*lane+1); row = 128B coalesced.
// ---------------------------------------------------------------------------

#define MAXN 100000
#define MAXE 1000000
#define D    64

__device__ int     g_deg[MAXN];       // zero at load; re-zeroed in fill_init
__device__ float   g_dinv[MAXN];
__device__ float   g_rdi[MAXN];
__device__ int     g_off[MAXN + 1];
__device__ int     g_rank[MAXE];
__device__ int     g_blocksums[128];
__device__ int     g_scanflag[128];
__device__ int     g_src[MAXE];
__device__ __half2 g_y0[MAXN * 32];   // 64 halfs per row = 32 half2
__device__ __half2 g_y1[MAXN * 32];
__device__ __half2 g_y2[MAXN * 32];

// ---------------------------------------------------------------------------
__device__ __forceinline__ bool block_is64(const int* __restrict__ p, int* s_flag) {
    if (threadIdx.x == 0) {
        int nz = 0;
        #pragma unroll 8
        for (int j = 1; j < 256; j += 2) nz += (p[j] != 0);
        *s_flag = (nz == 0);
    }
    __syncthreads();
    return *s_flag != 0;
}

// Histogram of destinations, 4 edges/thread; also records per-edge rank.
__global__ void k_hist(const void* __restrict__ ei, int E) {
    __shared__ int s64;
    bool is64 = block_is64((const int*)ei, &s64);
    if (blockIdx.x == 0 && threadIdx.x < 128) g_scanflag[threadIdx.x] = 0;
    int base = (blockIdx.x * blockDim.x + threadIdx.x) * 4;
    if (base >= E) return;
    int d0, d1, d2, d3;
    int n = E - base;
    if (is64) {
        const long long* p = (const long long*)ei + E + base;
        if (n >= 4) {
            longlong2 a = ((const longlong2*)p)[0];
            longlong2 b = ((const longlong2*)p)[1];
            d0 = (int)a.x; d1 = (int)a.y; d2 = (int)b.x; d3 = (int)b.y;
        } else {
            d0 = (int)p[0];
            d1 = (n > 1) ? (int)p[1] : -1;
            d2 = (n > 2) ? (int)p[2] : -1;
            d3 = -1;
        }
    } else {
        const int* p = (const int*)ei + E + base;
        if (n >= 4) {
            int4 a = *(const int4*)p;
            d0 = a.x; d1 = a.y; d2 = a.z; d3 = a.w;
        } else {
            d0 = p[0];
            d1 = (n > 1) ? p[1] : -1;
            d2 = (n > 2) ? p[2] : -1;
            d3 = -1;
        }
    }
    int r0 = atomicAdd(&g_deg[d0], 1);
    int r1 = (d1 >= 0) ? atomicAdd(&g_deg[d1], 1) : 0;
    int r2 = (d2 >= 0) ? atomicAdd(&g_deg[d2], 1) : 0;
    int r3 = (d3 >= 0) ? atomicAdd(&g_deg[d3], 1) : 0;
    if (n >= 4) {
        int4 r; r.x = r0; r.y = r1; r.z = r2; r.w = r3;
        *(int4*)(g_rank + base) = r;
    } else {
        g_rank[base] = r0;
        if (n > 1) g_rank[base + 1] = r1;
        if (n > 2) g_rank[base + 2] = r2;
    }
}

// Single-pass exclusive scan of deg -> off (+ dinv/rdi). All 98 blocks resident.
__global__ void k_scan(int N, int E) {
    __shared__ int sh[1024];
    int tid = threadIdx.x;
    int bid = blockIdx.x;
    int i = bid * 1024 + tid;
    int v = (i < N) ? g_deg[i] : 0;
    if (i < N) {
        float fv = (float)v;
        g_dinv[i] = (v > 0) ? rsqrtf(fv) : 0.0f;
        g_rdi[i]  = (v > 0) ? sqrtf(fv)  : 0.0f;
    }
    sh[tid] = v;
    __syncthreads();
    #pragma unroll
    for (int ofs = 1; ofs < 1024; ofs <<= 1) {
        int t = (tid >= ofs) ? sh[tid - ofs] : 0;
        __syncthreads();
        sh[tid] += t;
        __syncthreads();
    }
    int incl = sh[tid];
    if (tid == 1023) {
        g_blocksums[bid] = incl;
        __threadfence();
        ((volatile int*)g_scanflag)[bid] = 1;
    }
    __syncthreads();
    int part = 0;
    if (tid < bid) {
        while (((volatile int*)g_scanflag)[tid] == 0) {}
        __threadfence();
        part = g_blocksums[tid];
    }
    sh[tid] = part;
    __syncthreads();
    #pragma unroll
    for (int ofs = 512; ofs > 0; ofs >>= 1) {
        if (tid < ofs) sh[tid] += sh[tid + ofs];
        __syncthreads();
    }
    int base = sh[0];
    if (i < N) g_off[i] = base + incl - v;
    if (i == 0) g_off[N] = E;
}

// Fused: atomic-free CSR fill + y0/out init + deg reset.
__global__ void k_fill_init(const void* __restrict__ ei,
                            const float4* __restrict__ E0,
                            float4* __restrict__ out,
                            int E, int NQ, int N) {
    __shared__ int s64;
    bool is64 = block_is64((const int*)ei, &s64);
    int i = blockIdx.x * blockDim.x + threadIdx.x;
    if (i < N) g_deg[i] = 0;
    if (i < E) {
        int s, d;
        if (is64) {
            s = (int)((const long long*)ei)[i];
            d = (int)((const long long*)ei)[E + i];
        } else {
            s = ((const int*)ei)[i];
            d = ((const int*)ei)[E + i];
        }
        g_src[g_off[d] + g_rank[i]] = s;
    }
    if (i < NQ) {
        float4 v = E0[i];
        out[i] = v;
        float di = g_dinv[i >> 4];
        __half2 h0 = __floats2half2_rn(v.x * di, v.y * di);
        __half2 h1 = __floats2half2_rn(v.z * di, v.w * di);
        g_y0[2 * i]     = h0;
        g_y0[2 * i + 1] = h1;
    }
}

// WARP PER NODE. Stage <=32 src indices with one coalesced LDG, shfl-broadcast,
// gather 4 independent rows per unrolled step into 4 HADD2 banks.
__global__ void k_propagate(const __half2* __restrict__ y, __half2* __restrict__ yn,
                            int N, int E) {
    int node = blockIdx.x * 8 + (threadIdx.x >> 5);
    if (node >= N) return;
    int lane = threadIdx.x & 31;
    int beg = g_off[node];
    int end = g_off[node + 1];
    __half2 z = __float2half2_rn(0.f);
    __half2 a0 = z, a1 = z, a2 = z, a3 = z;
    for (int base = beg; base < end; base += 32) {
        int cnt = end - base; if (cnt > 32) cnt = 32;
        int li = base + lane; if (li >= E) li = E - 1;
        int s = g_src[li];
        int j = 0;
        for (; j + 3 < cnt; j += 4) {
            int sa = __shfl_sync(0xffffffffu, s, j);
            int sb = __shfl_sync(0xffffffffu, s, j + 1);
            int sc = __shfl_sync(0xffffffffu, s, j + 2);
            int sd = __shfl_sync(0xffffffffu, s, j + 3);
            __half2 va = y[sa * 32 + lane];
            __half2 vb = y[sb * 32 + lane];
            __half2 vc = y[sc * 32 + lane];
            __half2 vd = y[sd * 32 + lane];
            a0 = __hadd2(a0, va);
            a1 = __hadd2(a1, vb);
            a2 = __hadd2(a2, vc);
            a3 = __hadd2(a3, vd);
        }
        for (; j < cnt; j++) {
            int sa = __shfl_sync(0xffffffffu, s, j);
            a0 = __hadd2(a0, y[sa * 32 + lane]);
        }
    }
    float2 f0 = __half22float2(a0);
    float2 f1 = __half22float2(a1);
    float2 f2 = __half22float2(a2);
    float2 f3 = __half22float2(a3);
    float di2 = g_dinv[node];
    di2 *= di2;
    float rx = (f0.x + f1.x) + (f2.x + f3.x);
    float ry = (f0.y + f1.y) + (f2.y + f3.y);
    yn[node * 32 + lane] = __floats2half2_rn(di2 * rx, di2 * ry);
}

// Final layer fused with output: out = 0.25*(E0 + (y1+y2)*rdi + di*s3).
__global__ void k_propagate_last(const __half2* __restrict__ y2,
                                 const __half2* __restrict__ y1,
                                 const float2* __restrict__ E0,
                                 float2* __restrict__ out, int N, int E, int NH) {
    int node = blockIdx.x * 8 + (threadIdx.x >> 5);
    if (node >= N) return;
    int lane = threadIdx.x & 31;
    int beg = g_off[node];
    int end = g_off[node + 1];
    __half2 z = __float2half2_rn(0.f);
    __half2 a0 = z, a1 = z, a2 = z, a3 = z;
    for (int base = beg; base < end; base += 32) {
        int cnt = end - base; if (cnt > 32) cnt = 32;
        int li = base + lane; if (li >= E) li = E - 1;
        int s = g_src[li];
        int j = 0;
        for (; j + 3 < cnt; j += 4) {
            int sa = __shfl_sync(0xffffffffu, s, j);
            int sb = __shfl_sync(0xffffffffu, s, j + 1);
            int sc = __shfl_sync(0xffffffffu, s, j + 2);
            int sd = __shfl_sync(0xffffffffu, s, j + 3);
            __half2 va = y2[sa * 32 + lane];
            __half2 vb = y2[sb * 32 + lane];
            __half2 vc = y2[sc * 32 + lane];
            __half2 vd = y2[sd * 32 + lane];
            a0 = __hadd2(a0, va);
            a1 = __hadd2(a1, vb);
            a2 = __hadd2(a2, vc);
            a3 = __hadd2(a3, vd);
        }
        for (; j < cnt; j++) {
            int sa = __shfl_sync(0xffffffffu, s, j);
            a0 = __hadd2(a0, y2[sa * 32 + lane]);
        }
    }
    float2 f0 = __half22float2(a0);
    float2 f1 = __half22float2(a1);
    float2 f2 = __half22float2(a2);
    float2 f3 = __half22float2(a3);
    float sx = (f0.x + f1.x) + (f2.x + f3.x);
    float sy = (f0.y + f1.y) + (f2.y + f3.y);

    float di  = g_dinv[node];
    float rdi = g_rdi[node];
    int o = node * 32 + lane;
    float2 g1 = __half22float2(y1[o]);
    float2 g2 = __half22float2(y2[o]);
    float2 e0 = E0[o];
    float2 r;
    r.x = 0.25f * (e0.x + rdi * (g1.x + g2.x) + di * sx);
    r.y = 0.25f * (e0.y + rdi * (g1.y + g2.y) + di * sy);
    out[NH + o] = r;
}

// ---------------------------------------------------------------------------

extern "C" void kernel_launch(void* const* d_in, const int* in_sizes, int n_in,
                              void* d_out, int out_size) {
    const float4* E0 = (const float4*)d_in[0];
    const void*   ei = d_in[1];
    float4*       out = (float4*)d_out;

    int N  = in_sizes[0] / D;   // 100000
    int E  = in_sizes[1] / 2;   // 1000000
    int NQ = N * 16;            // float4 count per half of out
    int NH = N * 32;            // float2 count per half of out

    void *p0 = nullptr, *p1 = nullptr, *p2 = nullptr;
    cudaGetSymbolAddress(&p0, g_y0);
    cudaGetSymbolAddress(&p1, g_y1);
    cudaGetSymbolAddress(&p2, g_y2);
    __half2* y0 = (__half2*)p0;
    __half2* y1 = (__half2*)p1;
    __half2* y2 = (__half2*)p2;

    const int T = 256;
    int nb_scan = (N + 1023) / 1024;
    int nb_hist = ((E + 3) / 4 + T - 1) / T;

    k_hist<<<nb_hist, T>>>(ei, E);
    k_scan<<<nb_scan, 1024>>>(N, E);
    k_fill_init<<<(NQ + T - 1) / T, T>>>(ei, E0, out, E, NQ, N);

    int pg = (N + 7) / 8;   // 8 warps per block, warp per node
    k_propagate<<<pg, T>>>(y0, y1, N, E);
    k_propagate<<<pg, T>>>(y1, y2, N, E);
    k_propagate_last<<<pg, T>>>(y2, y1, (const float2*)d_in[0], (float2*)d_out, N, E, NH);
}